// round 11
// baseline (speedup 1.0000x reference)
#include <cuda_runtime.h>

#define HW   512
#define TX   64
#define TY   32
#define RSX  80   // TX + 16
#define RSY  48   // TY + 16
#define MSX  72   // TX + 8
#define MSY  40   // TY + 8
#define NT   512

// dynamic smem layout (floats)
#define OFF_SRAW 0
#define OFF_SHS  (RSY * RSX)                 // 3840
#define OFF_SRES (OFF_SHS + RSY * MSX)       // 7296
#define OFF_SHS2 (OFF_SRES + MSY * MSX)      // 10176
#define SMEM_FLOATS (OFF_SHS2 + MSY * TX)    // 12736
#define SMEM_BYTES (SMEM_FLOATS * 4)         // 50944

__device__ __forceinline__ int refl(int i) {
    i = ::abs(i);
    return i < HW ? i : (2 * HW - 2 - i);
}

// asinh(x) = sign(x) * log(|x| + sqrt(x^2+1)); sqrt via v*rsqrt(v) (v>=1)
__device__ __forceinline__ float fast_asinh(float x) {
    float ax = fabsf(x);
    float v  = fmaf(ax, ax, 1.0f);
    float s  = v * rsqrtf(v);
    float r  = __logf(ax + s);
    return copysignf(r, x);
}

__global__ __launch_bounds__(NT, 4) void imgnorm_kernel(
    const float* __restrict__ img, const float* __restrict__ bg,
    const float* __restrict__ thr, const float* __restrict__ scl,
    float* __restrict__ out)
{
    extern __shared__ float smem[];
    float* sraw = smem + OFF_SRAW;   // [48][80]
    float* shs  = smem + OFF_SHS;    // [48][72]  (aliased as sbox [32][64] after ph3)
    float* sres = smem + OFF_SRES;   // [40][72]
    float* shs2 = smem + OFF_SHS2;   // [40][64]
#define SRAW(r, c) sraw[(r) * RSX + (c)]
#define SHS(r, c)  shs [(r) * MSX + (c)]
#define SBOX(r, c) shs [(r) * TX  + (c)]
#define SRES(r, c) sres[(r) * MSX + (c)]
#define SHS2(r, c) shs2[(r) * TX  + (c)]
#define LD2(p)  (*(const float2*)&(p))
#define ST2(p)  (*(float2*)&(p))

    const int bc  = blockIdx.z;            // b*5 + c
    const int tx0 = blockIdx.x * TX;
    const int ty0 = blockIdx.y * TY;
    const float* im  = img + (size_t)bc * HW * HW;
    const float* bgp = bg  + (size_t)bc * HW * HW;
    const int tid = threadIdx.x;
    const float inv81 = 1.0f / 81.0f;

    // Per-thread output mapping (used in phases 1.5 and 5)
    const int row = tid >> 4;          // 0..31
    const int c4  = (tid & 15) << 2;   // 0..60
    const int gy  = ty0 + row;
    const int gx0 = tx0 + c4;
    const size_t CH = (size_t)HW * HW;
    const size_t p  = (size_t)bc * 7 * CH + (size_t)gy * HW + gx0;

    // Prefetch bg for this thread's 4 pixels — independent of all smem work.
    float bgv[4];
    *(float4*)bgv = *(const float4*)&bgp[(size_t)gy * HW + gx0];

    // Phase 1: load 48x80 raw tile. Interior blocks: vectorized LDG.128.
    const bool interior = (tx0 >= 8) && (tx0 + RSX - 8 <= HW) &&
                          (ty0 >= 8) && (ty0 + RSY - 8 <= HW);
    if (interior) {
        const float* base = im + (ty0 - 8) * HW + (tx0 - 8);
        for (int t = tid; t < RSY * (RSX / 4); t += NT) {       // 960 tasks
            int r = t / 20, c4i = (t - r * 20) * 4;
            *(float4*)&SRAW(r, c4i) = *(const float4*)&base[r * HW + c4i];
        }
    } else {
        for (int i = tid; i < RSY * RSX; i += NT) {             // 3840 tasks
            int r = i / RSX, c = i - r * RSX;
            SRAW(r, c) = im[refl(ty0 + r - 8) * HW + refl(tx0 + c - 8)];
        }
    }
    __syncthreads();

    // Phase 1.5: compute + store the 6 elementwise channels NOW, so the
    // 252 MB of store traffic drains while phases 2-4.5 run on smem/FMA.
    {
        const int cb = bc % 5;
        const float th0 = thr[cb * 3 + 0], th1 = thr[cb * 3 + 1], th2 = thr[cb * 3 + 2];
        const float sc0 = __expf(scl[cb * 3 + 0]);
        const float sc1 = __expf(scl[cb * 3 + 1]);
        const float sc2 = __expf(scl[cb * 3 + 2]);

        float raw[4];
        *(float4*)raw = *(const float4*)&SRAW(row + 8, c4 + 8);
        *(float4*)&out[p] = *(float4*)raw;

        float t4[4];
        #pragma unroll
        for (int j = 0; j < 4; j++) {
            float off = (raw[j] - bgv[j]) * rsqrtf(bgv[j]);
            t4[j] = __logf(fmaxf(off + 1.0f, 1.0f));
            bgv[j] = off;                       // reuse reg: keep off for l1
        }
        *(float4*)&out[p + 1 * CH] = *(float4*)t4;
        #pragma unroll
        for (int j = 0; j < 4; j++) t4[j] = __logf(fmaxf(bgv[j], 1.0f));
        *(float4*)&out[p + 2 * CH] = *(float4*)t4;
        #pragma unroll
        for (int j = 0; j < 4; j++) t4[j] = fast_asinh((raw[j] - th0) * sc0);
        *(float4*)&out[p + 4 * CH] = *(float4*)t4;
        #pragma unroll
        for (int j = 0; j < 4; j++) t4[j] = fast_asinh((raw[j] - th1) * sc1);
        *(float4*)&out[p + 5 * CH] = *(float4*)t4;
        #pragma unroll
        for (int j = 0; j < 4; j++) t4[j] = fast_asinh((raw[j] - th2) * sc2);
        *(float4*)&out[p + 6 * CH] = *(float4*)t4;
    }

    // Phase 2: horizontal 9-sums of raw, 48 rows x 72 cols (4 outs/task)
    for (int t = tid; t < RSY * (MSX / 4); t += NT) {           // 864 tasks
        int r = t / 18, c4i = (t - r * 18) * 4;
        float4 a = *(const float4*)&SRAW(r, c4i);
        float4 b = *(const float4*)&SRAW(r, c4i + 4);
        float4 c = *(const float4*)&SRAW(r, c4i + 8);
        float s0 = ((a.x + a.y) + (a.z + a.w)) + ((b.x + b.y) + (b.z + b.w)) + c.x;
        float s1 = s0 - a.x + c.y;
        float s2 = s1 - a.y + c.z;
        float s3 = s2 - a.z + c.w;
        *(float4*)&SHS(r, c4i) = make_float4(s0, s1, s2, s3);
    }
    __syncthreads();

    // Phase 3: vertical 9-sums -> mean -> res, 40x72 (float2 column-pairs)
    for (int t = tid; t < (MSY / 4) * (MSX / 2); t += NT) {     // 360 tasks
        int rg = t / 36, cp = t - rg * 36;
        int c = cp * 2, r0 = rg * 4;
        float2 a0 = LD2(SHS(r0, c)), a1 = LD2(SHS(r0 + 1, c));
        float2 s = make_float2(a0.x + a1.x, a0.y + a1.y);
        #pragma unroll
        for (int k = 2; k < 9; k++) {
            float2 w = LD2(SHS(r0 + k, c));
            s.x += w.x; s.y += w.y;
        }
        float2 rv = LD2(SRAW(r0 + 4, c + 4));
        ST2(SRES(r0 + 0, c)) = make_float2(rv.x - s.x * inv81, rv.y - s.y * inv81);
        float2 w9 = LD2(SHS(r0 + 9, c));
        s.x += w9.x - a0.x; s.y += w9.y - a0.y;
        rv = LD2(SRAW(r0 + 5, c + 4));
        ST2(SRES(r0 + 1, c)) = make_float2(rv.x - s.x * inv81, rv.y - s.y * inv81);
        float2 wA = LD2(SHS(r0 + 10, c));
        s.x += wA.x - a1.x; s.y += wA.y - a1.y;
        rv = LD2(SRAW(r0 + 6, c + 4));
        ST2(SRES(r0 + 2, c)) = make_float2(rv.x - s.x * inv81, rv.y - s.y * inv81);
        float2 wB = LD2(SHS(r0 + 11, c));
        float2 a2 = LD2(SHS(r0 + 2, c));
        s.x += wB.x - a2.x; s.y += wB.y - a2.y;
        rv = LD2(SRAW(r0 + 7, c + 4));
        ST2(SRES(r0 + 3, c)) = make_float2(rv.x - s.x * inv81, rv.y - s.y * inv81);
    }
    __syncthreads();

    // Phase 4: horizontal 9-sums of res^2, 40 rows x 64 cols (4 outs/task)
    for (int t = tid; t < MSY * (TX / 4); t += NT) {            // 640 tasks
        int r = t >> 4, c4i = (t & 15) * 4;
        float4 a = *(const float4*)&SRES(r, c4i);
        float4 b = *(const float4*)&SRES(r, c4i + 4);
        float4 c = *(const float4*)&SRES(r, c4i + 8);
        float q0 = a.x*a.x, q1 = a.y*a.y, q2 = a.z*a.z, q3 = a.w*a.w;
        float q4 = b.x*b.x, q5 = b.y*b.y, q6 = b.z*b.z, q7 = b.w*b.w;
        float q8 = c.x*c.x, q9 = c.y*c.y, q10 = c.z*c.z, q11 = c.w*c.w;
        float s0 = ((q0 + q1) + (q2 + q3)) + ((q4 + q5) + (q6 + q7)) + q8;
        float s1 = s0 - q0 + q9;
        float s2 = s1 - q1 + q10;
        float s3 = s2 - q2 + q11;
        *(float4*)&SHS2(r, c4i) = make_float4(s0, s1, s2, s3);
    }
    __syncthreads();

    // Phase 4.5: vertical 9-sum of shs2 -> SBOX (aliased over shs), 32x64.
    {
        int cp = tid & 31;
        int r0 = (tid >> 5) * 2;
        int c  = cp * 2;
        float2 a0 = LD2(SHS2(r0, c));
        float2 s = a0;
        #pragma unroll
        for (int k = 1; k < 9; k++) {
            float2 w = LD2(SHS2(r0 + k, c));
            s.x += w.x; s.y += w.y;
        }
        ST2(SBOX(r0 + 0, c)) = s;
        float2 w9 = LD2(SHS2(r0 + 9, c));
        s.x += w9.x - a0.x; s.y += w9.y - a0.y;
        ST2(SBOX(r0 + 1, c)) = s;
    }
    __syncthreads();

    // Phase 5: CLAHE only — tiny tail.
    {
        float res[4], vv[4], cl[4];
        *(float4*)res = *(const float4*)&SRES(row + 4, c4 + 4);
        *(float4*)vv  = *(const float4*)&SBOX(row, c4);
        #pragma unroll
        for (int j = 0; j < 4; j++)
            cl[j] = res[j] * rsqrtf(fmaxf(vv[j] * inv81, 1.0f));
        *(float4*)&out[p + 3 * CH] = *(float4*)cl;
    }
}

extern "C" void kernel_launch(void* const* d_in, const int* in_sizes, int n_in,
                              void* d_out, int out_size) {
    const float* img = (const float*)d_in[0];
    const float* bg  = (const float*)d_in[1];
    const float* thr = (const float*)d_in[2];
    const float* scl = (const float*)d_in[3];
    float* out = (float*)d_out;
    cudaFuncSetAttribute(imgnorm_kernel,
                         cudaFuncAttributeMaxDynamicSharedMemorySize, SMEM_BYTES);
    dim3 grid(HW / TX, HW / TY, 8 * 5);
    imgnorm_kernel<<<grid, NT, SMEM_BYTES>>>(img, bg, thr, scl, out);
}

// round 12
// speedup vs baseline: 1.0989x; 1.0989x over previous
#include <cuda_runtime.h>

#define HW   512
#define TX   64
#define TY   32
#define RSX  80   // TX + 16
#define RSY  48   // TY + 16
#define MSX  72   // TX + 8
#define MSY  40   // TY + 8
#define NT   512

// dynamic smem layout (floats)
#define OFF_SRAW 0
#define OFF_SHS  (RSY * RSX)                 // 3840   shs[48][72] / scs[32][72] alias
#define OFF_SRES (OFF_SHS + RSY * MSX)       // 7296   sres[40][72]
#define SMEM_FLOATS (OFF_SRES + MSY * MSX)   // 10176
#define SMEM_BYTES (SMEM_FLOATS * 4)         // 40704

__device__ __forceinline__ int refl(int i) {
    i = ::abs(i);
    return i < HW ? i : (2 * HW - 2 - i);
}

// asinh(x) = sign(x) * log(|x| + sqrt(x^2+1)); sqrt via v*rsqrt(v) (v>=1)
__device__ __forceinline__ float fast_asinh(float x) {
    float ax = fabsf(x);
    float v  = fmaf(ax, ax, 1.0f);
    float s  = v * rsqrtf(v);
    float r  = __logf(ax + s);
    return copysignf(r, x);
}

__global__ __launch_bounds__(NT, 4) void imgnorm_kernel(
    const float* __restrict__ img, const float* __restrict__ bg,
    const float* __restrict__ thr, const float* __restrict__ scl,
    float* __restrict__ out)
{
    extern __shared__ float smem[];
    float* sraw = smem + OFF_SRAW;   // [48][80]
    float* shs  = smem + OFF_SHS;    // [48][72] (phases 2-3); scs[32][72] (phase 4+)
    float* sres = smem + OFF_SRES;   // [40][72]
#define SRAW(r, c) sraw[(r) * RSX + (c)]
#define SHS(r, c)  shs [(r) * MSX + (c)]
#define SCS(r, c)  shs [(r) * MSX + (c)]
#define SRES(r, c) sres[(r) * MSX + (c)]
#define LD2(p)  (*(const float2*)&(p))
#define ST2(p)  (*(float2*)&(p))

    const int bc  = blockIdx.z;            // b*5 + c
    const int tx0 = blockIdx.x * TX;
    const int ty0 = blockIdx.y * TY;
    const float* im  = img + (size_t)bc * HW * HW;
    const float* bgp = bg  + (size_t)bc * HW * HW;
    const int tid = threadIdx.x;
    const float inv81 = 1.0f / 81.0f;

    // Per-thread output mapping (phases 1.5 and 5)
    const int row = tid >> 4;          // 0..31
    const int c4  = (tid & 15) << 2;   // 0..60
    const int gy  = ty0 + row;
    const int gx0 = tx0 + c4;
    const size_t CH = (size_t)HW * HW;
    const size_t p  = (size_t)bc * 7 * CH + (size_t)gy * HW + gx0;

    // Prefetch bg for this thread's 4 pixels — independent of all smem work.
    float bgv[4];
    *(float4*)bgv = *(const float4*)&bgp[(size_t)gy * HW + gx0];

    // Phase 1: load 48x80 raw tile. Interior blocks: vectorized LDG.128.
    const bool interior = (tx0 >= 8) && (tx0 + RSX - 8 <= HW) &&
                          (ty0 >= 8) && (ty0 + RSY - 8 <= HW);
    if (interior) {
        const float* base = im + (ty0 - 8) * HW + (tx0 - 8);
        for (int t = tid; t < RSY * (RSX / 4); t += NT) {       // 960 tasks
            int r = t / 20, c4i = (t - r * 20) * 4;
            *(float4*)&SRAW(r, c4i) = *(const float4*)&base[r * HW + c4i];
        }
    } else {
        for (int i = tid; i < RSY * RSX; i += NT) {             // 3840 tasks
            int r = i / RSX, c = i - r * RSX;
            SRAW(r, c) = im[refl(ty0 + r - 8) * HW + refl(tx0 + c - 8)];
        }
    }
    __syncthreads();

    // Phase 1.5: compute + store the 6 elementwise channels NOW, so their
    // store traffic drains while phases 2-4 run on smem/FMA.
    {
        const int cb = bc % 5;
        const float th0 = thr[cb * 3 + 0], th1 = thr[cb * 3 + 1], th2 = thr[cb * 3 + 2];
        const float sc0 = __expf(scl[cb * 3 + 0]);
        const float sc1 = __expf(scl[cb * 3 + 1]);
        const float sc2 = __expf(scl[cb * 3 + 2]);

        float raw[4];
        *(float4*)raw = *(const float4*)&SRAW(row + 8, c4 + 8);
        *(float4*)&out[p] = *(float4*)raw;

        float t4[4];
        #pragma unroll
        for (int j = 0; j < 4; j++) {
            float off = (raw[j] - bgv[j]) * rsqrtf(bgv[j]);
            t4[j] = __logf(fmaxf(off + 1.0f, 1.0f));
            bgv[j] = off;                       // keep off for l1
        }
        *(float4*)&out[p + 1 * CH] = *(float4*)t4;
        #pragma unroll
        for (int j = 0; j < 4; j++) t4[j] = __logf(fmaxf(bgv[j], 1.0f));
        *(float4*)&out[p + 2 * CH] = *(float4*)t4;
        #pragma unroll
        for (int j = 0; j < 4; j++) t4[j] = fast_asinh((raw[j] - th0) * sc0);
        *(float4*)&out[p + 4 * CH] = *(float4*)t4;
        #pragma unroll
        for (int j = 0; j < 4; j++) t4[j] = fast_asinh((raw[j] - th1) * sc1);
        *(float4*)&out[p + 5 * CH] = *(float4*)t4;
        #pragma unroll
        for (int j = 0; j < 4; j++) t4[j] = fast_asinh((raw[j] - th2) * sc2);
        *(float4*)&out[p + 6 * CH] = *(float4*)t4;
    }

    // Phase 2: horizontal 9-sums of raw, 48 rows x 72 cols (4 outs/task)
    for (int t = tid; t < RSY * (MSX / 4); t += NT) {           // 864 tasks
        int r = t / 18, c4i = (t - r * 18) * 4;
        float4 a = *(const float4*)&SRAW(r, c4i);
        float4 b = *(const float4*)&SRAW(r, c4i + 4);
        float4 c = *(const float4*)&SRAW(r, c4i + 8);
        float s0 = ((a.x + a.y) + (a.z + a.w)) + ((b.x + b.y) + (b.z + b.w)) + c.x;
        float s1 = s0 - a.x + c.y;
        float s2 = s1 - a.y + c.z;
        float s3 = s2 - a.z + c.w;
        *(float4*)&SHS(r, c4i) = make_float4(s0, s1, s2, s3);
    }
    __syncthreads();

    // Phase 3: vertical 9-sums -> mean -> res, 40x72 (float2 column-pairs)
    for (int t = tid; t < (MSY / 4) * (MSX / 2); t += NT) {     // 360 tasks
        int rg = t / 36, cp = t - rg * 36;
        int c = cp * 2, r0 = rg * 4;
        float2 a0 = LD2(SHS(r0, c)), a1 = LD2(SHS(r0 + 1, c));
        float2 s = make_float2(a0.x + a1.x, a0.y + a1.y);
        #pragma unroll
        for (int k = 2; k < 9; k++) {
            float2 w = LD2(SHS(r0 + k, c));
            s.x += w.x; s.y += w.y;
        }
        float2 rv = LD2(SRAW(r0 + 4, c + 4));
        ST2(SRES(r0 + 0, c)) = make_float2(rv.x - s.x * inv81, rv.y - s.y * inv81);
        float2 w9 = LD2(SHS(r0 + 9, c));
        s.x += w9.x - a0.x; s.y += w9.y - a0.y;
        rv = LD2(SRAW(r0 + 5, c + 4));
        ST2(SRES(r0 + 1, c)) = make_float2(rv.x - s.x * inv81, rv.y - s.y * inv81);
        float2 wA = LD2(SHS(r0 + 10, c));
        s.x += wA.x - a1.x; s.y += wA.y - a1.y;
        rv = LD2(SRAW(r0 + 6, c + 4));
        ST2(SRES(r0 + 2, c)) = make_float2(rv.x - s.x * inv81, rv.y - s.y * inv81);
        float2 wB = LD2(SHS(r0 + 11, c));
        float2 a2 = LD2(SHS(r0 + 2, c));
        s.x += wB.x - a2.x; s.y += wB.y - a2.y;
        rv = LD2(SRAW(r0 + 7, c + 4));
        ST2(SRES(r0 + 3, c)) = make_float2(rv.x - s.x * inv81, rv.y - s.y * inv81);
    }
    __syncthreads();

    // Phase 4: VERTICAL-FIRST variance sums. scs[r][c] = sum_k res^2[r+k][c],
    // 32 rows x 72 cols, float2 column-pairs, 4-row sliding groups.
    // scs aliases shs (dead after phase 3; barrier above orders it).
    for (int t = tid; t < 8 * (MSX / 2); t += NT) {             // 288 tasks
        int rg = t / 36, cp = t - rg * 36;
        int c = cp * 2, r0 = rg * 4;
        float2 w0 = LD2(SRES(r0, c)), w1 = LD2(SRES(r0 + 1, c));
        float2 q0 = make_float2(w0.x * w0.x, w0.y * w0.y);
        float2 q1 = make_float2(w1.x * w1.x, w1.y * w1.y);
        float2 s = make_float2(q0.x + q1.x, q0.y + q1.y);
        #pragma unroll
        for (int k = 2; k < 9; k++) {
            float2 w = LD2(SRES(r0 + k, c));
            s.x = fmaf(w.x, w.x, s.x); s.y = fmaf(w.y, w.y, s.y);
        }
        ST2(SCS(r0 + 0, c)) = s;
        float2 w9 = LD2(SRES(r0 + 9, c));
        s.x = fmaf(w9.x, w9.x, s.x) - q0.x; s.y = fmaf(w9.y, w9.y, s.y) - q0.y;
        ST2(SCS(r0 + 1, c)) = s;
        float2 wA = LD2(SRES(r0 + 10, c));
        s.x = fmaf(wA.x, wA.x, s.x) - q1.x; s.y = fmaf(wA.y, wA.y, s.y) - q1.y;
        ST2(SCS(r0 + 2, c)) = s;
        float2 wB = LD2(SRES(r0 + 11, c));
        float2 w2 = LD2(SRES(r0 + 2, c));
        s.x = fmaf(wB.x, wB.x, s.x) - w2.x * w2.x;
        s.y = fmaf(wB.y, wB.y, s.y) - w2.y * w2.y;
        ST2(SCS(r0 + 3, c)) = s;
    }
    __syncthreads();

    // Phase 5: horizontal 9-sum of scs in registers + CLAHE store.
    {
        float q[12];
        *(float4*)&q[0] = *(const float4*)&SCS(row, c4);
        *(float4*)&q[4] = *(const float4*)&SCS(row, c4 + 4);
        *(float4*)&q[8] = *(const float4*)&SCS(row, c4 + 8);
        float s0 = ((q[0] + q[1]) + (q[2] + q[3])) +
                   ((q[4] + q[5]) + (q[6] + q[7])) + q[8];
        float s1 = s0 - q[0] + q[9];
        float s2 = s1 - q[1] + q[10];
        float s3 = s2 - q[2] + q[11];

        float res4[4], cl[4];
        *(float4*)res4 = *(const float4*)&SRES(row + 4, c4 + 4);
        cl[0] = res4[0] * rsqrtf(fmaxf(s0 * inv81, 1.0f));
        cl[1] = res4[1] * rsqrtf(fmaxf(s1 * inv81, 1.0f));
        cl[2] = res4[2] * rsqrtf(fmaxf(s2 * inv81, 1.0f));
        cl[3] = res4[3] * rsqrtf(fmaxf(s3 * inv81, 1.0f));
        *(float4*)&out[p + 3 * CH] = *(float4*)cl;
    }
}

extern "C" void kernel_launch(void* const* d_in, const int* in_sizes, int n_in,
                              void* d_out, int out_size) {
    const float* img = (const float*)d_in[0];
    const float* bg  = (const float*)d_in[1];
    const float* thr = (const float*)d_in[2];
    const float* scl = (const float*)d_in[3];
    float* out = (float*)d_out;
    cudaFuncSetAttribute(imgnorm_kernel,
                         cudaFuncAttributeMaxDynamicSharedMemorySize, SMEM_BYTES);
    dim3 grid(HW / TX, HW / TY, 8 * 5);
    imgnorm_kernel<<<grid, NT, SMEM_BYTES>>>(img, bg, thr, scl, out);
}

// round 13
// speedup vs baseline: 1.1994x; 1.0914x over previous
#include <cuda_runtime.h>

#define HW   512
#define TX   64
#define TY   32
#define RSX  80   // TX + 16
#define RSY  48   // TY + 16
#define MSX  72   // TX + 8
#define MSY  40   // TY + 8
#define NT   512

// dynamic smem layout (floats)
#define OFF_SRAW 0
#define OFF_SHS  (RSY * RSX)                 // 3840   shs[48][72] / scs[32][72] alias
#define OFF_SRES (OFF_SHS + RSY * MSX)       // 7296   sres[40][72]
#define SMEM_FLOATS (OFF_SRES + MSY * MSX)   // 10176
#define SMEM_BYTES (SMEM_FLOATS * 4)         // 40704

__device__ __forceinline__ int refl(int i) {
    i = ::abs(i);
    return i < HW ? i : (2 * HW - 2 - i);
}

// asinh(x) = sign(x) * log(|x| + sqrt(x^2+1)); sqrt via v*rsqrt(v) (v>=1)
__device__ __forceinline__ float fast_asinh(float x) {
    float ax = fabsf(x);
    float v  = fmaf(ax, ax, 1.0f);
    float s  = v * rsqrtf(v);
    float r  = __logf(ax + s);
    return copysignf(r, x);
}

__global__ __launch_bounds__(NT, 4) void imgnorm_kernel(
    const float* __restrict__ img, const float* __restrict__ bg,
    const float* __restrict__ thr, const float* __restrict__ scl,
    float* __restrict__ out)
{
    extern __shared__ float smem[];
    float* sraw = smem + OFF_SRAW;   // [48][80]
    float* shs  = smem + OFF_SHS;    // [48][72] (phases 2-3); scs[32][72] (phase 4+)
    float* sres = smem + OFF_SRES;   // [40][72]
#define SRAW(r, c) sraw[(r) * RSX + (c)]
#define SHS(r, c)  shs [(r) * MSX + (c)]
#define SCS(r, c)  shs [(r) * MSX + (c)]
#define SRES(r, c) sres[(r) * MSX + (c)]
#define LD2(p)  (*(const float2*)&(p))
#define ST2(p)  (*(float2*)&(p))

    const int bc  = blockIdx.z;            // b*5 + c
    const int tx0 = blockIdx.x * TX;
    const int ty0 = blockIdx.y * TY;
    const float* im  = img + (size_t)bc * HW * HW;
    const float* bgp = bg  + (size_t)bc * HW * HW;
    const int tid = threadIdx.x;
    const float inv81 = 1.0f / 81.0f;

    // Per-thread output mapping (phases 1.5 and 5)
    const int row = tid >> 4;          // 0..31
    const int c4  = (tid & 15) << 2;   // 0..60
    const int gy  = ty0 + row;
    const int gx0 = tx0 + c4;
    const size_t CH = (size_t)HW * HW;
    const size_t p  = (size_t)bc * 7 * CH + (size_t)gy * HW + gx0;

    // Earliest: issue own-center + bg global loads (deepest latency first) and
    // the broadcast constant loads. Phase 1.5 depends ONLY on these — not on
    // the tile barrier.
    float raw[4], bgv[4];
    *(float4*)raw = *(const float4*)&im [(size_t)gy * HW + gx0];
    *(float4*)bgv = *(const float4*)&bgp[(size_t)gy * HW + gx0];
    const int cb = bc % 5;
    const float th0 = thr[cb * 3 + 0], th1 = thr[cb * 3 + 1], th2 = thr[cb * 3 + 2];
    const float sc0 = __expf(scl[cb * 3 + 0]);
    const float sc1 = __expf(scl[cb * 3 + 1]);
    const float sc2 = __expf(scl[cb * 3 + 2]);

    // Phase 1: load 48x80 raw tile into smem. Interior blocks: LDG.128.
    const bool interior = (tx0 >= 8) && (tx0 + RSX - 8 <= HW) &&
                          (ty0 >= 8) && (ty0 + RSY - 8 <= HW);
    if (interior) {
        const float* base = im + (ty0 - 8) * HW + (tx0 - 8);
        for (int t = tid; t < RSY * (RSX / 4); t += NT) {       // 960 tasks
            int r = t / 20, c4i = (t - r * 20) * 4;
            *(float4*)&SRAW(r, c4i) = *(const float4*)&base[r * HW + c4i];
        }
    } else {
        for (int i = tid; i < RSY * RSX; i += NT) {             // 3840 tasks
            int r = i / RSX, c = i - r * RSX;
            SRAW(r, c) = im[refl(ty0 + r - 8) * HW + refl(tx0 + c - 8)];
        }
    }

    // Phase 1.5 (pre-barrier): 6 elementwise channels from own registers.
    // Runs while other threads' tile loads are still in flight.
    {
        *(float4*)&out[p] = *(float4*)raw;
        float t4[4], off4[4];
        #pragma unroll
        for (int j = 0; j < 4; j++) {
            float off = (raw[j] - bgv[j]) * rsqrtf(bgv[j]);
            t4[j] = __logf(fmaxf(off + 1.0f, 1.0f));
            off4[j] = off;
        }
        *(float4*)&out[p + 1 * CH] = *(float4*)t4;
        #pragma unroll
        for (int j = 0; j < 4; j++) t4[j] = __logf(fmaxf(off4[j], 1.0f));
        *(float4*)&out[p + 2 * CH] = *(float4*)t4;
        #pragma unroll
        for (int j = 0; j < 4; j++) t4[j] = fast_asinh((raw[j] - th0) * sc0);
        *(float4*)&out[p + 4 * CH] = *(float4*)t4;
        #pragma unroll
        for (int j = 0; j < 4; j++) t4[j] = fast_asinh((raw[j] - th1) * sc1);
        *(float4*)&out[p + 5 * CH] = *(float4*)t4;
        #pragma unroll
        for (int j = 0; j < 4; j++) t4[j] = fast_asinh((raw[j] - th2) * sc2);
        *(float4*)&out[p + 6 * CH] = *(float4*)t4;
    }
    __syncthreads();

    // Phase 2: horizontal 9-sums of raw, 48 rows x 72 cols (4 outs/task)
    for (int t = tid; t < RSY * (MSX / 4); t += NT) {           // 864 tasks
        int r = t / 18, c4i = (t - r * 18) * 4;
        float4 a = *(const float4*)&SRAW(r, c4i);
        float4 b = *(const float4*)&SRAW(r, c4i + 4);
        float4 c = *(const float4*)&SRAW(r, c4i + 8);
        float s0 = ((a.x + a.y) + (a.z + a.w)) + ((b.x + b.y) + (b.z + b.w)) + c.x;
        float s1 = s0 - a.x + c.y;
        float s2 = s1 - a.y + c.z;
        float s3 = s2 - a.z + c.w;
        *(float4*)&SHS(r, c4i) = make_float4(s0, s1, s2, s3);
    }
    __syncthreads();

    // Phase 3: vertical 9-sums -> mean -> res, 40x72 (float2 column-pairs)
    for (int t = tid; t < (MSY / 4) * (MSX / 2); t += NT) {     // 360 tasks
        int rg = t / 36, cp = t - rg * 36;
        int c = cp * 2, r0 = rg * 4;
        float2 a0 = LD2(SHS(r0, c)), a1 = LD2(SHS(r0 + 1, c));
        float2 s = make_float2(a0.x + a1.x, a0.y + a1.y);
        #pragma unroll
        for (int k = 2; k < 9; k++) {
            float2 w = LD2(SHS(r0 + k, c));
            s.x += w.x; s.y += w.y;
        }
        float2 rv = LD2(SRAW(r0 + 4, c + 4));
        ST2(SRES(r0 + 0, c)) = make_float2(rv.x - s.x * inv81, rv.y - s.y * inv81);
        float2 w9 = LD2(SHS(r0 + 9, c));
        s.x += w9.x - a0.x; s.y += w9.y - a0.y;
        rv = LD2(SRAW(r0 + 5, c + 4));
        ST2(SRES(r0 + 1, c)) = make_float2(rv.x - s.x * inv81, rv.y - s.y * inv81);
        float2 wA = LD2(SHS(r0 + 10, c));
        s.x += wA.x - a1.x; s.y += wA.y - a1.y;
        rv = LD2(SRAW(r0 + 6, c + 4));
        ST2(SRES(r0 + 2, c)) = make_float2(rv.x - s.x * inv81, rv.y - s.y * inv81);
        float2 wB = LD2(SHS(r0 + 11, c));
        float2 a2 = LD2(SHS(r0 + 2, c));
        s.x += wB.x - a2.x; s.y += wB.y - a2.y;
        rv = LD2(SRAW(r0 + 7, c + 4));
        ST2(SRES(r0 + 3, c)) = make_float2(rv.x - s.x * inv81, rv.y - s.y * inv81);
    }
    __syncthreads();

    // Phase 4: VERTICAL-FIRST variance sums. scs[r][c] = sum_k res^2[r+k][c],
    // 32 rows x 72 cols, float2 column-pairs, 4-row sliding groups.
    // scs aliases shs (dead after phase 3; barrier above orders it).
    for (int t = tid; t < 8 * (MSX / 2); t += NT) {             // 288 tasks
        int rg = t / 36, cp = t - rg * 36;
        int c = cp * 2, r0 = rg * 4;
        float2 w0 = LD2(SRES(r0, c)), w1 = LD2(SRES(r0 + 1, c));
        float2 q0 = make_float2(w0.x * w0.x, w0.y * w0.y);
        float2 q1 = make_float2(w1.x * w1.x, w1.y * w1.y);
        float2 s = make_float2(q0.x + q1.x, q0.y + q1.y);
        #pragma unroll
        for (int k = 2; k < 9; k++) {
            float2 w = LD2(SRES(r0 + k, c));
            s.x = fmaf(w.x, w.x, s.x); s.y = fmaf(w.y, w.y, s.y);
        }
        ST2(SCS(r0 + 0, c)) = s;
        float2 w9 = LD2(SRES(r0 + 9, c));
        s.x = fmaf(w9.x, w9.x, s.x) - q0.x; s.y = fmaf(w9.y, w9.y, s.y) - q0.y;
        ST2(SCS(r0 + 1, c)) = s;
        float2 wA = LD2(SRES(r0 + 10, c));
        s.x = fmaf(wA.x, wA.x, s.x) - q1.x; s.y = fmaf(wA.y, wA.y, s.y) - q1.y;
        ST2(SCS(r0 + 2, c)) = s;
        float2 wB = LD2(SRES(r0 + 11, c));
        float2 w2 = LD2(SRES(r0 + 2, c));
        s.x = fmaf(wB.x, wB.x, s.x) - w2.x * w2.x;
        s.y = fmaf(wB.y, wB.y, s.y) - w2.y * w2.y;
        ST2(SCS(r0 + 3, c)) = s;
    }
    __syncthreads();

    // Phase 5: horizontal 9-sum of scs in registers + CLAHE store.
    {
        float q[12];
        *(float4*)&q[0] = *(const float4*)&SCS(row, c4);
        *(float4*)&q[4] = *(const float4*)&SCS(row, c4 + 4);
        *(float4*)&q[8] = *(const float4*)&SCS(row, c4 + 8);
        float s0 = ((q[0] + q[1]) + (q[2] + q[3])) +
                   ((q[4] + q[5]) + (q[6] + q[7])) + q[8];
        float s1 = s0 - q[0] + q[9];
        float s2 = s1 - q[1] + q[10];
        float s3 = s2 - q[2] + q[11];

        float res4[4], cl[4];
        *(float4*)res4 = *(const float4*)&SRES(row + 4, c4 + 4);
        cl[0] = res4[0] * rsqrtf(fmaxf(s0 * inv81, 1.0f));
        cl[1] = res4[1] * rsqrtf(fmaxf(s1 * inv81, 1.0f));
        cl[2] = res4[2] * rsqrtf(fmaxf(s2 * inv81, 1.0f));
        cl[3] = res4[3] * rsqrtf(fmaxf(s3 * inv81, 1.0f));
        *(float4*)&out[p + 3 * CH] = *(float4*)cl;
    }
}

extern "C" void kernel_launch(void* const* d_in, const int* in_sizes, int n_in,
                              void* d_out, int out_size) {
    const float* img = (const float*)d_in[0];
    const float* bg  = (const float*)d_in[1];
    const float* thr = (const float*)d_in[2];
    const float* scl = (const float*)d_in[3];
    float* out = (float*)d_out;
    cudaFuncSetAttribute(imgnorm_kernel,
                         cudaFuncAttributeMaxDynamicSharedMemorySize, SMEM_BYTES);
    dim3 grid(HW / TX, HW / TY, 8 * 5);
    imgnorm_kernel<<<grid, NT, SMEM_BYTES>>>(img, bg, thr, scl, out);
}

// round 14
// speedup vs baseline: 1.2206x; 1.0177x over previous
#include <cuda_runtime.h>

#define HW   512
#define TX   64
#define TY   32
#define RSX  80   // TX + 16
#define RSY  48   // TY + 16
#define MSX  72   // TX + 8
#define MSY  40   // TY + 8
#define NT   512

// dynamic smem layout (floats)
#define OFF_SRAW 0
#define OFF_SHS  (RSY * RSX)                 // 3840   shs[48][72] / scs[32][72] alias
#define OFF_SRES (OFF_SHS + RSY * MSX)       // 7296   sres[40][72]
#define SMEM_FLOATS (OFF_SRES + MSY * MSX)   // 10176
#define SMEM_BYTES (SMEM_FLOATS * 4)         // 40704

__device__ __forceinline__ int refl(int i) {
    i = ::abs(i);
    return i < HW ? i : (2 * HW - 2 - i);
}

// asinh(x) = sign(x) * log(|x| + sqrt(x^2+1)); sqrt via v*rsqrt(v) (v>=1)
__device__ __forceinline__ float fast_asinh(float x) {
    float ax = fabsf(x);
    float v  = fmaf(ax, ax, 1.0f);
    float s  = v * rsqrtf(v);
    float r  = __logf(ax + s);
    return copysignf(r, x);
}

__global__ __launch_bounds__(NT, 4) void imgnorm_kernel(
    const float* __restrict__ img, const float* __restrict__ bg,
    const float* __restrict__ thr, const float* __restrict__ scl,
    float* __restrict__ out)
{
    extern __shared__ float smem[];
    float* sraw = smem + OFF_SRAW;   // [48][80]
    float* shs  = smem + OFF_SHS;    // [48][72] (phases 2-3); scs[32][72] (phase 4+)
    float* sres = smem + OFF_SRES;   // [40][72]
#define SRAW(r, c) sraw[(r) * RSX + (c)]
#define SHS(r, c)  shs [(r) * MSX + (c)]
#define SCS(r, c)  shs [(r) * MSX + (c)]
#define SRES(r, c) sres[(r) * MSX + (c)]
#define LD2(p)  (*(const float2*)&(p))
#define ST2(p)  (*(float2*)&(p))

    const int bc  = blockIdx.z;            // b*5 + c
    const int tx0 = blockIdx.x * TX;
    const int ty0 = blockIdx.y * TY;
    const float* im  = img + (size_t)bc * HW * HW;
    const float* bgp = bg  + (size_t)bc * HW * HW;
    const int tid = threadIdx.x;
    const float inv81 = 1.0f / 81.0f;

    // Per-thread output mapping (phases 1.5 and 5)
    const int row = tid >> 4;          // 0..31
    const int c4  = (tid & 15) << 2;   // 0..60
    const int gy  = ty0 + row;
    const int gx0 = tx0 + c4;
    const size_t CH = (size_t)HW * HW;
    const size_t p  = (size_t)bc * 7 * CH + (size_t)gy * HW + gx0;

    // Earliest: issue own-center + bg global loads (deepest latency first) and
    // the broadcast constant loads. Phase 1.5 depends ONLY on these.
    float raw[4], bgv[4];
    *(float4*)raw = *(const float4*)&im [(size_t)gy * HW + gx0];
    *(float4*)bgv = *(const float4*)&bgp[(size_t)gy * HW + gx0];
    const int cb = bc % 5;
    const float th0 = thr[cb * 3 + 0], th1 = thr[cb * 3 + 1], th2 = thr[cb * 3 + 2];
    const float sc0 = __expf(scl[cb * 3 + 0]);
    const float sc1 = __expf(scl[cb * 3 + 1]);
    const float sc2 = __expf(scl[cb * 3 + 2]);

    // Phase 1: load 48x80 raw tile into smem. Interior blocks: LDG.128.
    const bool interior = (tx0 >= 8) && (tx0 + RSX - 8 <= HW) &&
                          (ty0 >= 8) && (ty0 + RSY - 8 <= HW);
    if (interior) {
        const float* base = im + (ty0 - 8) * HW + (tx0 - 8);
        for (int t = tid; t < RSY * (RSX / 4); t += NT) {       // 960 tasks
            int r = t / 20, c4i = (t - r * 20) * 4;
            *(float4*)&SRAW(r, c4i) = *(const float4*)&base[r * HW + c4i];
        }
    } else {
        for (int i = tid; i < RSY * RSX; i += NT) {             // 3840 tasks
            int r = i / RSX, c = i - r * RSX;
            SRAW(r, c) = im[refl(ty0 + r - 8) * HW + refl(tx0 + c - 8)];
        }
    }

    // Phase 1.5 (pre-barrier): 6 elementwise channels from own registers.
    // Streaming stores: output is write-once — evict-first keeps L2 for the
    // reusable input halo lines.
    {
        __stcs((float4*)&out[p], *(const float4*)raw);
        float t4[4], off4[4];
        #pragma unroll
        for (int j = 0; j < 4; j++) {
            float off = (raw[j] - bgv[j]) * rsqrtf(bgv[j]);
            t4[j] = __logf(fmaxf(off + 1.0f, 1.0f));
            off4[j] = off;
        }
        __stcs((float4*)&out[p + 1 * CH], *(const float4*)t4);
        #pragma unroll
        for (int j = 0; j < 4; j++) t4[j] = __logf(fmaxf(off4[j], 1.0f));
        __stcs((float4*)&out[p + 2 * CH], *(const float4*)t4);
        #pragma unroll
        for (int j = 0; j < 4; j++) t4[j] = fast_asinh((raw[j] - th0) * sc0);
        __stcs((float4*)&out[p + 4 * CH], *(const float4*)t4);
        #pragma unroll
        for (int j = 0; j < 4; j++) t4[j] = fast_asinh((raw[j] - th1) * sc1);
        __stcs((float4*)&out[p + 5 * CH], *(const float4*)t4);
        #pragma unroll
        for (int j = 0; j < 4; j++) t4[j] = fast_asinh((raw[j] - th2) * sc2);
        __stcs((float4*)&out[p + 6 * CH], *(const float4*)t4);
    }
    __syncthreads();

    // Phase 2: horizontal 9-sums of raw, 48 rows x 72 cols (4 outs/task)
    for (int t = tid; t < RSY * (MSX / 4); t += NT) {           // 864 tasks
        int r = t / 18, c4i = (t - r * 18) * 4;
        float4 a = *(const float4*)&SRAW(r, c4i);
        float4 b = *(const float4*)&SRAW(r, c4i + 4);
        float4 c = *(const float4*)&SRAW(r, c4i + 8);
        float s0 = ((a.x + a.y) + (a.z + a.w)) + ((b.x + b.y) + (b.z + b.w)) + c.x;
        float s1 = s0 - a.x + c.y;
        float s2 = s1 - a.y + c.z;
        float s3 = s2 - a.z + c.w;
        *(float4*)&SHS(r, c4i) = make_float4(s0, s1, s2, s3);
    }
    __syncthreads();

    // Phase 3: vertical 9-sums -> mean -> res, 40x72 (float2 column-pairs)
    for (int t = tid; t < (MSY / 4) * (MSX / 2); t += NT) {     // 360 tasks
        int rg = t / 36, cp = t - rg * 36;
        int c = cp * 2, r0 = rg * 4;
        float2 a0 = LD2(SHS(r0, c)), a1 = LD2(SHS(r0 + 1, c));
        float2 s = make_float2(a0.x + a1.x, a0.y + a1.y);
        #pragma unroll
        for (int k = 2; k < 9; k++) {
            float2 w = LD2(SHS(r0 + k, c));
            s.x += w.x; s.y += w.y;
        }
        float2 rv = LD2(SRAW(r0 + 4, c + 4));
        ST2(SRES(r0 + 0, c)) = make_float2(rv.x - s.x * inv81, rv.y - s.y * inv81);
        float2 w9 = LD2(SHS(r0 + 9, c));
        s.x += w9.x - a0.x; s.y += w9.y - a0.y;
        rv = LD2(SRAW(r0 + 5, c + 4));
        ST2(SRES(r0 + 1, c)) = make_float2(rv.x - s.x * inv81, rv.y - s.y * inv81);
        float2 wA = LD2(SHS(r0 + 10, c));
        s.x += wA.x - a1.x; s.y += wA.y - a1.y;
        rv = LD2(SRAW(r0 + 6, c + 4));
        ST2(SRES(r0 + 2, c)) = make_float2(rv.x - s.x * inv81, rv.y - s.y * inv81);
        float2 wB = LD2(SHS(r0 + 11, c));
        float2 a2 = LD2(SHS(r0 + 2, c));
        s.x += wB.x - a2.x; s.y += wB.y - a2.y;
        rv = LD2(SRAW(r0 + 7, c + 4));
        ST2(SRES(r0 + 3, c)) = make_float2(rv.x - s.x * inv81, rv.y - s.y * inv81);
    }
    __syncthreads();

    // Phase 4: VERTICAL-FIRST variance sums. scs[r][c] = sum_k res^2[r+k][c],
    // 32 rows x 72 cols, float2 column-pairs, 4-row sliding groups.
    for (int t = tid; t < 8 * (MSX / 2); t += NT) {             // 288 tasks
        int rg = t / 36, cp = t - rg * 36;
        int c = cp * 2, r0 = rg * 4;
        float2 w0 = LD2(SRES(r0, c)), w1 = LD2(SRES(r0 + 1, c));
        float2 q0 = make_float2(w0.x * w0.x, w0.y * w0.y);
        float2 q1 = make_float2(w1.x * w1.x, w1.y * w1.y);
        float2 s = make_float2(q0.x + q1.x, q0.y + q1.y);
        #pragma unroll
        for (int k = 2; k < 9; k++) {
            float2 w = LD2(SRES(r0 + k, c));
            s.x = fmaf(w.x, w.x, s.x); s.y = fmaf(w.y, w.y, s.y);
        }
        ST2(SCS(r0 + 0, c)) = s;
        float2 w9 = LD2(SRES(r0 + 9, c));
        s.x = fmaf(w9.x, w9.x, s.x) - q0.x; s.y = fmaf(w9.y, w9.y, s.y) - q0.y;
        ST2(SCS(r0 + 1, c)) = s;
        float2 wA = LD2(SRES(r0 + 10, c));
        s.x = fmaf(wA.x, wA.x, s.x) - q1.x; s.y = fmaf(wA.y, wA.y, s.y) - q1.y;
        ST2(SCS(r0 + 2, c)) = s;
        float2 wB = LD2(SRES(r0 + 11, c));
        float2 w2 = LD2(SRES(r0 + 2, c));
        s.x = fmaf(wB.x, wB.x, s.x) - w2.x * w2.x;
        s.y = fmaf(wB.y, wB.y, s.y) - w2.y * w2.y;
        ST2(SCS(r0 + 3, c)) = s;
    }
    __syncthreads();

    // Phase 5: horizontal 9-sum of scs in registers + CLAHE store.
    {
        float q[12];
        *(float4*)&q[0] = *(const float4*)&SCS(row, c4);
        *(float4*)&q[4] = *(const float4*)&SCS(row, c4 + 4);
        *(float4*)&q[8] = *(const float4*)&SCS(row, c4 + 8);
        float s0 = ((q[0] + q[1]) + (q[2] + q[3])) +
                   ((q[4] + q[5]) + (q[6] + q[7])) + q[8];
        float s1 = s0 - q[0] + q[9];
        float s2 = s1 - q[1] + q[10];
        float s3 = s2 - q[2] + q[11];

        float res4[4], cl[4];
        *(float4*)res4 = *(const float4*)&SRES(row + 4, c4 + 4);
        cl[0] = res4[0] * rsqrtf(fmaxf(s0 * inv81, 1.0f));
        cl[1] = res4[1] * rsqrtf(fmaxf(s1 * inv81, 1.0f));
        cl[2] = res4[2] * rsqrtf(fmaxf(s2 * inv81, 1.0f));
        cl[3] = res4[3] * rsqrtf(fmaxf(s3 * inv81, 1.0f));
        __stcs((float4*)&out[p + 3 * CH], *(const float4*)cl);
    }
}

extern "C" void kernel_launch(void* const* d_in, const int* in_sizes, int n_in,
                              void* d_out, int out_size) {
    const float* img = (const float*)d_in[0];
    const float* bg  = (const float*)d_in[1];
    const float* thr = (const float*)d_in[2];
    const float* scl = (const float*)d_in[3];
    float* out = (float*)d_out;
    cudaFuncSetAttribute(imgnorm_kernel,
                         cudaFuncAttributeMaxDynamicSharedMemorySize, SMEM_BYTES);
    dim3 grid(HW / TX, HW / TY, 8 * 5);
    imgnorm_kernel<<<grid, NT, SMEM_BYTES>>>(img, bg, thr, scl, out);
}

// round 15
// speedup vs baseline: 1.2738x; 1.0436x over previous
#include <cuda_runtime.h>

#define HW   512
#define TX   64
#define TY   32
#define RSX  80   // TX + 16
#define RSY  48   // TY + 16
#define MSX  72   // TX + 8
#define MSY  40   // TY + 8
#define NT   512

// dynamic smem layout (floats)
#define OFF_SRAW 0
#define OFF_SHS  (RSY * RSX)                 // 3840   shs[48][72] / scs[32][72] alias
#define OFF_SRES (OFF_SHS + RSY * MSX)       // 7296   sres[40][72]
#define SMEM_FLOATS (OFF_SRES + MSY * MSX)   // 10176
#define SMEM_BYTES (SMEM_FLOATS * 4)         // 40704

__device__ __forceinline__ int refl(int i) {
    i = ::abs(i);
    return i < HW ? i : (2 * HW - 2 - i);
}

// asinh(x) = sign(x) * log(|x| + sqrt(x^2+1)); sqrt via v*rsqrt(v) (v>=1)
__device__ __forceinline__ float fast_asinh(float x) {
    float ax = fabsf(x);
    float v  = fmaf(ax, ax, 1.0f);
    float s  = v * rsqrtf(v);
    float r  = __logf(ax + s);
    return copysignf(r, x);
}

__global__ __launch_bounds__(NT, 4) void imgnorm_kernel(
    const float* __restrict__ img, const float* __restrict__ bg,
    const float* __restrict__ thr, const float* __restrict__ scl,
    float* __restrict__ out)
{
    extern __shared__ float smem[];
    float* sraw = smem + OFF_SRAW;   // [48][80]
    float* shs  = smem + OFF_SHS;    // [48][72] (phases 2-3); scs[32][72] (phase 4+)
    float* sres = smem + OFF_SRES;   // [40][72]
#define SRAW(r, c) sraw[(r) * RSX + (c)]
#define SHS(r, c)  shs [(r) * MSX + (c)]
#define SCS(r, c)  shs [(r) * MSX + (c)]
#define SRES(r, c) sres[(r) * MSX + (c)]
#define LD2(p)  (*(const float2*)&(p))
#define ST2(p)  (*(float2*)&(p))

    const int bc  = blockIdx.z;            // b*5 + c
    const int tx0 = blockIdx.x * TX;
    const int ty0 = blockIdx.y * TY;
    const float* im  = img + (size_t)bc * HW * HW;
    const float* bgp = bg  + (size_t)bc * HW * HW;
    const int tid = threadIdx.x;
    const float inv81 = 1.0f / 81.0f;

    // Per-thread output mapping (phases 1.5 and 5)
    const int row = tid >> 4;          // 0..31
    const int c4  = (tid & 15) << 2;   // 0..60
    const int gy  = ty0 + row;
    const int gx0 = tx0 + c4;
    const size_t CH = (size_t)HW * HW;
    const size_t p  = (size_t)bc * 7 * CH + (size_t)gy * HW + gx0;

    // Earliest: issue own-center + bg global loads (deepest latency first) and
    // the broadcast constant loads. Phase 1.5 depends ONLY on these.
    float raw[4], bgv[4];
    *(float4*)raw = *(const float4*)&im [(size_t)gy * HW + gx0];
    *(float4*)bgv = *(const float4*)&bgp[(size_t)gy * HW + gx0];
    const int cb = bc % 5;
    const float th0 = thr[cb * 3 + 0], th1 = thr[cb * 3 + 1], th2 = thr[cb * 3 + 2];
    const float sc0 = __expf(scl[cb * 3 + 0]);
    const float sc1 = __expf(scl[cb * 3 + 1]);
    const float sc2 = __expf(scl[cb * 3 + 2]);

    // Phase 1: load 48x80 raw tile into smem.
    // y handled with per-row reflected index (rows stay contiguous in x).
    // Only x-border CTAs (blockIdx.x 0 or last) take per-group predication,
    // and there only 2/20 column groups need scalar reflect.
    const bool xin = (tx0 >= 8) && (tx0 + RSX - 8 <= HW);
    if (xin) {
        const float* base = im + (tx0 - 8);
        for (int t = tid; t < RSY * (RSX / 4); t += NT) {       // 960 tasks
            int r = t / 20, c4i = (t - r * 20) * 4;
            int gr = refl(ty0 + r - 8);
            *(float4*)&SRAW(r, c4i) = *(const float4*)&base[gr * HW + c4i];
        }
    } else {
        for (int t = tid; t < RSY * (RSX / 4); t += NT) {       // 960 tasks
            int r = t / 20, c4i = (t - r * 20) * 4;
            int gr = refl(ty0 + r - 8);
            int gx = tx0 - 8 + c4i;
            if (gx >= 0 && gx + 3 < HW) {
                *(float4*)&SRAW(r, c4i) = *(const float4*)&im[gr * HW + gx];
            } else {
                SRAW(r, c4i + 0) = im[gr * HW + refl(gx + 0)];
                SRAW(r, c4i + 1) = im[gr * HW + refl(gx + 1)];
                SRAW(r, c4i + 2) = im[gr * HW + refl(gx + 2)];
                SRAW(r, c4i + 3) = im[gr * HW + refl(gx + 3)];
            }
        }
    }

    // Phase 1.5 (pre-barrier): 6 elementwise channels from own registers.
    // Streaming stores: output is write-once — evict-first keeps L2 for the
    // reusable input halo lines. Runs while tile loads are still in flight.
    {
        __stcs((float4*)&out[p], *(const float4*)raw);
        float t4[4], off4[4];
        #pragma unroll
        for (int j = 0; j < 4; j++) {
            float off = (raw[j] - bgv[j]) * rsqrtf(bgv[j]);
            t4[j] = __logf(fmaxf(off + 1.0f, 1.0f));
            off4[j] = off;
        }
        __stcs((float4*)&out[p + 1 * CH], *(const float4*)t4);
        #pragma unroll
        for (int j = 0; j < 4; j++) t4[j] = __logf(fmaxf(off4[j], 1.0f));
        __stcs((float4*)&out[p + 2 * CH], *(const float4*)t4);
        #pragma unroll
        for (int j = 0; j < 4; j++) t4[j] = fast_asinh((raw[j] - th0) * sc0);
        __stcs((float4*)&out[p + 4 * CH], *(const float4*)t4);
        #pragma unroll
        for (int j = 0; j < 4; j++) t4[j] = fast_asinh((raw[j] - th1) * sc1);
        __stcs((float4*)&out[p + 5 * CH], *(const float4*)t4);
        #pragma unroll
        for (int j = 0; j < 4; j++) t4[j] = fast_asinh((raw[j] - th2) * sc2);
        __stcs((float4*)&out[p + 6 * CH], *(const float4*)t4);
    }
    __syncthreads();

    // Phase 2: horizontal 9-sums of raw, 48 rows x 72 cols (4 outs/task)
    for (int t = tid; t < RSY * (MSX / 4); t += NT) {           // 864 tasks
        int r = t / 18, c4i = (t - r * 18) * 4;
        float4 a = *(const float4*)&SRAW(r, c4i);
        float4 b = *(const float4*)&SRAW(r, c4i + 4);
        float4 c = *(const float4*)&SRAW(r, c4i + 8);
        float s0 = ((a.x + a.y) + (a.z + a.w)) + ((b.x + b.y) + (b.z + b.w)) + c.x;
        float s1 = s0 - a.x + c.y;
        float s2 = s1 - a.y + c.z;
        float s3 = s2 - a.z + c.w;
        *(float4*)&SHS(r, c4i) = make_float4(s0, s1, s2, s3);
    }
    __syncthreads();

    // Phase 3: vertical 9-sums -> mean -> res, 40x72 (float2 column-pairs)
    for (int t = tid; t < (MSY / 4) * (MSX / 2); t += NT) {     // 360 tasks
        int rg = t / 36, cp = t - rg * 36;
        int c = cp * 2, r0 = rg * 4;
        float2 a0 = LD2(SHS(r0, c)), a1 = LD2(SHS(r0 + 1, c));
        float2 s = make_float2(a0.x + a1.x, a0.y + a1.y);
        #pragma unroll
        for (int k = 2; k < 9; k++) {
            float2 w = LD2(SHS(r0 + k, c));
            s.x += w.x; s.y += w.y;
        }
        float2 rv = LD2(SRAW(r0 + 4, c + 4));
        ST2(SRES(r0 + 0, c)) = make_float2(rv.x - s.x * inv81, rv.y - s.y * inv81);
        float2 w9 = LD2(SHS(r0 + 9, c));
        s.x += w9.x - a0.x; s.y += w9.y - a0.y;
        rv = LD2(SRAW(r0 + 5, c + 4));
        ST2(SRES(r0 + 1, c)) = make_float2(rv.x - s.x * inv81, rv.y - s.y * inv81);
        float2 wA = LD2(SHS(r0 + 10, c));
        s.x += wA.x - a1.x; s.y += wA.y - a1.y;
        rv = LD2(SRAW(r0 + 6, c + 4));
        ST2(SRES(r0 + 2, c)) = make_float2(rv.x - s.x * inv81, rv.y - s.y * inv81);
        float2 wB = LD2(SHS(r0 + 11, c));
        float2 a2 = LD2(SHS(r0 + 2, c));
        s.x += wB.x - a2.x; s.y += wB.y - a2.y;
        rv = LD2(SRAW(r0 + 7, c + 4));
        ST2(SRES(r0 + 3, c)) = make_float2(rv.x - s.x * inv81, rv.y - s.y * inv81);
    }
    __syncthreads();

    // Phase 4: VERTICAL-FIRST variance sums. scs[r][c] = sum_k res^2[r+k][c],
    // 32 rows x 72 cols, float2 column-pairs, 4-row sliding groups.
    for (int t = tid; t < 8 * (MSX / 2); t += NT) {             // 288 tasks
        int rg = t / 36, cp = t - rg * 36;
        int c = cp * 2, r0 = rg * 4;
        float2 w0 = LD2(SRES(r0, c)), w1 = LD2(SRES(r0 + 1, c));
        float2 q0 = make_float2(w0.x * w0.x, w0.y * w0.y);
        float2 q1 = make_float2(w1.x * w1.x, w1.y * w1.y);
        float2 s = make_float2(q0.x + q1.x, q0.y + q1.y);
        #pragma unroll
        for (int k = 2; k < 9; k++) {
            float2 w = LD2(SRES(r0 + k, c));
            s.x = fmaf(w.x, w.x, s.x); s.y = fmaf(w.y, w.y, s.y);
        }
        ST2(SCS(r0 + 0, c)) = s;
        float2 w9 = LD2(SRES(r0 + 9, c));
        s.x = fmaf(w9.x, w9.x, s.x) - q0.x; s.y = fmaf(w9.y, w9.y, s.y) - q0.y;
        ST2(SCS(r0 + 1, c)) = s;
        float2 wA = LD2(SRES(r0 + 10, c));
        s.x = fmaf(wA.x, wA.x, s.x) - q1.x; s.y = fmaf(wA.y, wA.y, s.y) - q1.y;
        ST2(SCS(r0 + 2, c)) = s;
        float2 wB = LD2(SRES(r0 + 11, c));
        float2 w2 = LD2(SRES(r0 + 2, c));
        s.x = fmaf(wB.x, wB.x, s.x) - w2.x * w2.x;
        s.y = fmaf(wB.y, wB.y, s.y) - w2.y * w2.y;
        ST2(SCS(r0 + 3, c)) = s;
    }
    __syncthreads();

    // Phase 5: horizontal 9-sum of scs in registers + CLAHE store.
    {
        float q[12];
        *(float4*)&q[0] = *(const float4*)&SCS(row, c4);
        *(float4*)&q[4] = *(const float4*)&SCS(row, c4 + 4);
        *(float4*)&q[8] = *(const float4*)&SCS(row, c4 + 8);
        float s0 = ((q[0] + q[1]) + (q[2] + q[3])) +
                   ((q[4] + q[5]) + (q[6] + q[7])) + q[8];
        float s1 = s0 - q[0] + q[9];
        float s2 = s1 - q[1] + q[10];
        float s3 = s2 - q[2] + q[11];

        float res4[4], cl[4];
        *(float4*)res4 = *(const float4*)&SRES(row + 4, c4 + 4);
        cl[0] = res4[0] * rsqrtf(fmaxf(s0 * inv81, 1.0f));
        cl[1] = res4[1] * rsqrtf(fmaxf(s1 * inv81, 1.0f));
        cl[2] = res4[2] * rsqrtf(fmaxf(s2 * inv81, 1.0f));
        cl[3] = res4[3] * rsqrtf(fmaxf(s3 * inv81, 1.0f));
        __stcs((float4*)&out[p + 3 * CH], *(const float4*)cl);
    }
}

extern "C" void kernel_launch(void* const* d_in, const int* in_sizes, int n_in,
                              void* d_out, int out_size) {
    const float* img = (const float*)d_in[0];
    const float* bg  = (const float*)d_in[1];
    const float* thr = (const float*)d_in[2];
    const float* scl = (const float*)d_in[3];
    float* out = (float*)d_out;
    cudaFuncSetAttribute(imgnorm_kernel,
                         cudaFuncAttributeMaxDynamicSharedMemorySize, SMEM_BYTES);
    dim3 grid(HW / TX, HW / TY, 8 * 5);
    imgnorm_kernel<<<grid, NT, SMEM_BYTES>>>(img, bg, thr, scl, out);
}

// round 16
// speedup vs baseline: 1.3398x; 1.0518x over previous
#include <cuda_runtime.h>

#define HW   512
#define TX   64
#define TY   32
#define RSX  80   // TX + 16
#define RSY  48   // TY + 16
#define MSX  72   // TX + 8
#define MSY  40   // TY + 8
#define NT   512

// dynamic smem layout (floats)
#define OFF_SRAW 0
#define OFF_SHS  (RSY * RSX)                 // 3840   shs[48][72] / scs[32][72] alias
#define OFF_SRES (OFF_SHS + RSY * MSX)       // 7296   sres[40][72]
#define SMEM_FLOATS (OFF_SRES + MSY * MSX)   // 10176
#define SMEM_BYTES (SMEM_FLOATS * 4)         // 40704

__device__ __forceinline__ int refl(int i) {
    i = ::abs(i);
    return i < HW ? i : (2 * HW - 2 - i);
}

// asinh(x) = sign(x) * log(|x| + sqrt(x^2+1)); sqrt via v*rsqrt(v) (v>=1)
__device__ __forceinline__ float fast_asinh(float x) {
    float ax = fabsf(x);
    float v  = fmaf(ax, ax, 1.0f);
    float s  = v * rsqrtf(v);
    float r  = __logf(ax + s);
    return copysignf(r, x);
}

__global__ __launch_bounds__(NT, 4) void imgnorm_kernel(
    const float* __restrict__ img, const float* __restrict__ bg,
    const float* __restrict__ thr, const float* __restrict__ scl,
    float* __restrict__ out)
{
    extern __shared__ float smem[];
    float* sraw = smem + OFF_SRAW;   // [48][80]
    float* shs  = smem + OFF_SHS;    // [48][72] (phases 2-3); scs[32][72] (phase 4+)
    float* sres = smem + OFF_SRES;   // [40][72]
#define SRAW(r, c) sraw[(r) * RSX + (c)]
#define SHS(r, c)  shs [(r) * MSX + (c)]
#define SCS(r, c)  shs [(r) * MSX + (c)]
#define SRES(r, c) sres[(r) * MSX + (c)]
#define LD2(p)  (*(const float2*)&(p))
#define ST2(p)  (*(float2*)&(p))

    const int bc  = blockIdx.z;            // b*5 + c
    const int tx0 = blockIdx.x * TX;
    const int ty0 = blockIdx.y * TY;
    const float* im  = img + (size_t)bc * HW * HW;
    const float* bgp = bg  + (size_t)bc * HW * HW;
    const int tid = threadIdx.x;
    const float inv81 = 1.0f / 81.0f;

    // Per-thread output mapping (phases 1.5 and 5)
    const int row = tid >> 4;          // 0..31
    const int c4  = (tid & 15) << 2;   // 0..60
    const int gy  = ty0 + row;
    const int gx0 = tx0 + c4;
    const size_t CH = (size_t)HW * HW;
    const size_t p  = (size_t)bc * 7 * CH + (size_t)gy * HW + gx0;

    // Earliest: issue own-center + bg global loads (deepest latency first) and
    // the broadcast constant loads. Phase 1.5 depends ONLY on these.
    float raw[4], bgv[4];
    *(float4*)raw = *(const float4*)&im [(size_t)gy * HW + gx0];
    *(float4*)bgv = *(const float4*)&bgp[(size_t)gy * HW + gx0];
    const int cb = bc % 5;
    const float th0 = thr[cb * 3 + 0], th1 = thr[cb * 3 + 1], th2 = thr[cb * 3 + 2];
    const float sc0 = __expf(scl[cb * 3 + 0]);
    const float sc1 = __expf(scl[cb * 3 + 1]);
    const float sc2 = __expf(scl[cb * 3 + 2]);

    // Phase 1: load ONLY the halo of the 48x80 tile (448 float4 tasks):
    //   t in [0,320): top 8 + bottom 8 rows, full 20 column-groups
    //   t in [320,448): middle 32 rows, column-groups {0,1,18,19}
    // The 32x64 center comes from each thread's raw registers (no 2nd LDG).
    // y via per-row reflect (rows contiguous); x via cheap per-group predicate.
    if (tid < 448) {
        int r, c4i;
        if (tid < 320) {
            int rr = tid / 20;
            r = (rr < 8) ? rr : rr + 32;
            c4i = (tid - rr * 20) * 4;
        } else {
            int u = tid - 320;
            r = 8 + (u >> 2);
            int g = u & 3;
            c4i = ((g < 2) ? g : g + 16) * 4;
        }
        int gr = refl(ty0 + r - 8);
        int gx = tx0 - 8 + c4i;
        if (gx >= 0 && gx + 3 < HW) {
            *(float4*)&SRAW(r, c4i) = *(const float4*)&im[gr * HW + gx];
        } else {
            SRAW(r, c4i + 0) = im[gr * HW + refl(gx + 0)];
            SRAW(r, c4i + 1) = im[gr * HW + refl(gx + 1)];
            SRAW(r, c4i + 2) = im[gr * HW + refl(gx + 2)];
            SRAW(r, c4i + 3) = im[gr * HW + refl(gx + 3)];
        }
    }
    // Center: one STS.128 from registers per thread.
    *(float4*)&SRAW(row + 8, c4 + 8) = *(const float4*)raw;

    // Phase 1.5 (pre-barrier): 6 elementwise channels from own registers.
    // Streaming stores: output is write-once — evict-first keeps L2 for the
    // reusable input halo lines. Runs while halo loads are still in flight.
    {
        __stcs((float4*)&out[p], *(const float4*)raw);
        float t4[4], off4[4];
        #pragma unroll
        for (int j = 0; j < 4; j++) {
            float off = (raw[j] - bgv[j]) * rsqrtf(bgv[j]);
            t4[j] = __logf(fmaxf(off + 1.0f, 1.0f));
            off4[j] = off;
        }
        __stcs((float4*)&out[p + 1 * CH], *(const float4*)t4);
        #pragma unroll
        for (int j = 0; j < 4; j++) t4[j] = __logf(fmaxf(off4[j], 1.0f));
        __stcs((float4*)&out[p + 2 * CH], *(const float4*)t4);
        #pragma unroll
        for (int j = 0; j < 4; j++) t4[j] = fast_asinh((raw[j] - th0) * sc0);
        __stcs((float4*)&out[p + 4 * CH], *(const float4*)t4);
        #pragma unroll
        for (int j = 0; j < 4; j++) t4[j] = fast_asinh((raw[j] - th1) * sc1);
        __stcs((float4*)&out[p + 5 * CH], *(const float4*)t4);
        #pragma unroll
        for (int j = 0; j < 4; j++) t4[j] = fast_asinh((raw[j] - th2) * sc2);
        __stcs((float4*)&out[p + 6 * CH], *(const float4*)t4);
    }
    __syncthreads();

    // Phase 2: horizontal 9-sums of raw, 48 rows x 72 cols (4 outs/task)
    for (int t = tid; t < RSY * (MSX / 4); t += NT) {           // 864 tasks
        int r = t / 18, c4i = (t - r * 18) * 4;
        float4 a = *(const float4*)&SRAW(r, c4i);
        float4 b = *(const float4*)&SRAW(r, c4i + 4);
        float4 c = *(const float4*)&SRAW(r, c4i + 8);
        float s0 = ((a.x + a.y) + (a.z + a.w)) + ((b.x + b.y) + (b.z + b.w)) + c.x;
        float s1 = s0 - a.x + c.y;
        float s2 = s1 - a.y + c.z;
        float s3 = s2 - a.z + c.w;
        *(float4*)&SHS(r, c4i) = make_float4(s0, s1, s2, s3);
    }
    __syncthreads();

    // Phase 3: vertical 9-sums -> mean -> res, 40x72 (float2 column-pairs)
    for (int t = tid; t < (MSY / 4) * (MSX / 2); t += NT) {     // 360 tasks
        int rg = t / 36, cp = t - rg * 36;
        int c = cp * 2, r0 = rg * 4;
        float2 a0 = LD2(SHS(r0, c)), a1 = LD2(SHS(r0 + 1, c));
        float2 s = make_float2(a0.x + a1.x, a0.y + a1.y);
        #pragma unroll
        for (int k = 2; k < 9; k++) {
            float2 w = LD2(SHS(r0 + k, c));
            s.x += w.x; s.y += w.y;
        }
        float2 rv = LD2(SRAW(r0 + 4, c + 4));
        ST2(SRES(r0 + 0, c)) = make_float2(rv.x - s.x * inv81, rv.y - s.y * inv81);
        float2 w9 = LD2(SHS(r0 + 9, c));
        s.x += w9.x - a0.x; s.y += w9.y - a0.y;
        rv = LD2(SRAW(r0 + 5, c + 4));
        ST2(SRES(r0 + 1, c)) = make_float2(rv.x - s.x * inv81, rv.y - s.y * inv81);
        float2 wA = LD2(SHS(r0 + 10, c));
        s.x += wA.x - a1.x; s.y += wA.y - a1.y;
        rv = LD2(SRAW(r0 + 6, c + 4));
        ST2(SRES(r0 + 2, c)) = make_float2(rv.x - s.x * inv81, rv.y - s.y * inv81);
        float2 wB = LD2(SHS(r0 + 11, c));
        float2 a2 = LD2(SHS(r0 + 2, c));
        s.x += wB.x - a2.x; s.y += wB.y - a2.y;
        rv = LD2(SRAW(r0 + 7, c + 4));
        ST2(SRES(r0 + 3, c)) = make_float2(rv.x - s.x * inv81, rv.y - s.y * inv81);
    }
    __syncthreads();

    // Phase 4: VERTICAL-FIRST variance sums. scs[r][c] = sum_k res^2[r+k][c],
    // 32 rows x 72 cols, float2 column-pairs, 4-row sliding groups.
    for (int t = tid; t < 8 * (MSX / 2); t += NT) {             // 288 tasks
        int rg = t / 36, cp = t - rg * 36;
        int c = cp * 2, r0 = rg * 4;
        float2 w0 = LD2(SRES(r0, c)), w1 = LD2(SRES(r0 + 1, c));
        float2 q0 = make_float2(w0.x * w0.x, w0.y * w0.y);
        float2 q1 = make_float2(w1.x * w1.x, w1.y * w1.y);
        float2 s = make_float2(q0.x + q1.x, q0.y + q1.y);
        #pragma unroll
        for (int k = 2; k < 9; k++) {
            float2 w = LD2(SRES(r0 + k, c));
            s.x = fmaf(w.x, w.x, s.x); s.y = fmaf(w.y, w.y, s.y);
        }
        ST2(SCS(r0 + 0, c)) = s;
        float2 w9 = LD2(SRES(r0 + 9, c));
        s.x = fmaf(w9.x, w9.x, s.x) - q0.x; s.y = fmaf(w9.y, w9.y, s.y) - q0.y;
        ST2(SCS(r0 + 1, c)) = s;
        float2 wA = LD2(SRES(r0 + 10, c));
        s.x = fmaf(wA.x, wA.x, s.x) - q1.x; s.y = fmaf(wA.y, wA.y, s.y) - q1.y;
        ST2(SCS(r0 + 2, c)) = s;
        float2 wB = LD2(SRES(r0 + 11, c));
        float2 w2 = LD2(SRES(r0 + 2, c));
        s.x = fmaf(wB.x, wB.x, s.x) - w2.x * w2.x;
        s.y = fmaf(wB.y, wB.y, s.y) - w2.y * w2.y;
        ST2(SCS(r0 + 3, c)) = s;
    }
    __syncthreads();

    // Phase 5: horizontal 9-sum of scs in registers + CLAHE store.
    {
        float q[12];
        *(float4*)&q[0] = *(const float4*)&SCS(row, c4);
        *(float4*)&q[4] = *(const float4*)&SCS(row, c4 + 4);
        *(float4*)&q[8] = *(const float4*)&SCS(row, c4 + 8);
        float s0 = ((q[0] + q[1]) + (q[2] + q[3])) +
                   ((q[4] + q[5]) + (q[6] + q[7])) + q[8];
        float s1 = s0 - q[0] + q[9];
        float s2 = s1 - q[1] + q[10];
        float s3 = s2 - q[2] + q[11];

        float res4[4], cl[4];
        *(float4*)res4 = *(const float4*)&SRES(row + 4, c4 + 4);
        cl[0] = res4[0] * rsqrtf(fmaxf(s0 * inv81, 1.0f));
        cl[1] = res4[1] * rsqrtf(fmaxf(s1 * inv81, 1.0f));
        cl[2] = res4[2] * rsqrtf(fmaxf(s2 * inv81, 1.0f));
        cl[3] = res4[3] * rsqrtf(fmaxf(s3 * inv81, 1.0f));
        __stcs((float4*)&out[p + 3 * CH], *(const float4*)cl);
    }
}

extern "C" void kernel_launch(void* const* d_in, const int* in_sizes, int n_in,
                              void* d_out, int out_size) {
    const float* img = (const float*)d_in[0];
    const float* bg  = (const float*)d_in[1];
    const float* thr = (const float*)d_in[2];
    const float* scl = (const float*)d_in[3];
    float* out = (float*)d_out;
    cudaFuncSetAttribute(imgnorm_kernel,
                         cudaFuncAttributeMaxDynamicSharedMemorySize, SMEM_BYTES);
    dim3 grid(HW / TX, HW / TY, 8 * 5);
    imgnorm_kernel<<<grid, NT, SMEM_BYTES>>>(img, bg, thr, scl, out);
}

// round 17
// speedup vs baseline: 1.3533x; 1.0101x over previous
#include <cuda_runtime.h>

#define HW   512
#define TX   64
#define TY   32
#define RSX  80   // TX + 16
#define RSY  48   // TY + 16
#define MSX  72   // TX + 8
#define MSY  40   // TY + 8
#define NT   512

// dynamic smem layout (floats)
#define OFF_SRAW 0
#define OFF_SHS  (RSY * RSX)                 // 3840   shs[48][72] / scs[32][72] alias
#define OFF_SRES (OFF_SHS + RSY * MSX)       // 7296   sres[40][72]
#define SMEM_FLOATS (OFF_SRES + MSY * MSX)   // 10176
#define SMEM_BYTES (SMEM_FLOATS * 4)         // 40704

__device__ __forceinline__ int refl(int i) {
    i = ::abs(i);
    return i < HW ? i : (2 * HW - 2 - i);
}

// asinh(x) = sign(x) * log(|x| + sqrt(x^2+1)); sqrt via v*rsqrt(v) (v>=1)
__device__ __forceinline__ float fast_asinh(float x) {
    float ax = fabsf(x);
    float v  = fmaf(ax, ax, 1.0f);
    float s  = v * rsqrtf(v);
    float r  = __logf(ax + s);
    return copysignf(r, x);
}

__global__ __launch_bounds__(NT, 4) void imgnorm_kernel(
    const float* __restrict__ img, const float* __restrict__ bg,
    const float* __restrict__ thr, const float* __restrict__ scl,
    float* __restrict__ out)
{
    extern __shared__ float smem[];
    float* sraw = smem + OFF_SRAW;   // [48][80]
    float* shs  = smem + OFF_SHS;    // [48][72] (phases 2-3); scs[32][72] (phase 4+)
    float* sres = smem + OFF_SRES;   // [40][72]
#define SRAW(r, c) sraw[(r) * RSX + (c)]
#define SHS(r, c)  shs [(r) * MSX + (c)]
#define SCS(r, c)  shs [(r) * MSX + (c)]
#define SRES(r, c) sres[(r) * MSX + (c)]
#define LD2(p)  (*(const float2*)&(p))
#define ST2(p)  (*(float2*)&(p))

    const int bc  = blockIdx.z;            // b*5 + c
    const int tx0 = blockIdx.x * TX;
    const int ty0 = blockIdx.y * TY;
    const float* im  = img + (size_t)bc * HW * HW;
    const float* bgp = bg  + (size_t)bc * HW * HW;
    const int tid = threadIdx.x;
    const float inv81 = 1.0f / 81.0f;

    // Per-thread output mapping (phases 1.5 and 5)
    const int row = tid >> 4;          // 0..31
    const int c4  = (tid & 15) << 2;   // 0..60
    const int gy  = ty0 + row;
    const int gx0 = tx0 + c4;
    const size_t CH = (size_t)HW * HW;
    const size_t p  = (size_t)bc * 7 * CH + (size_t)gy * HW + gx0;

    // Earliest: issue own-center + bg global loads (deepest latency first) and
    // the broadcast constant loads. Phase 1.5 depends ONLY on these.
    float raw[4], bgv[4];
    *(float4*)raw = *(const float4*)&im [(size_t)gy * HW + gx0];
    *(float4*)bgv = *(const float4*)&bgp[(size_t)gy * HW + gx0];
    const int cb = bc % 5;
    const float th0 = thr[cb * 3 + 0], th1 = thr[cb * 3 + 1], th2 = thr[cb * 3 + 2];
    const float sc0 = __expf(scl[cb * 3 + 0]);
    const float sc1 = __expf(scl[cb * 3 + 1]);
    const float sc2 = __expf(scl[cb * 3 + 2]);

    // Phase 1: load ONLY the halo of the 48x80 tile (448 float4 tasks).
    if (tid < 448) {
        int r, c4i;
        if (tid < 320) {
            int rr = tid / 20;
            r = (rr < 8) ? rr : rr + 32;
            c4i = (tid - rr * 20) * 4;
        } else {
            int u = tid - 320;
            r = 8 + (u >> 2);
            int g = u & 3;
            c4i = ((g < 2) ? g : g + 16) * 4;
        }
        int gr = refl(ty0 + r - 8);
        int gx = tx0 - 8 + c4i;
        if (gx >= 0 && gx + 3 < HW) {
            *(float4*)&SRAW(r, c4i) = *(const float4*)&im[gr * HW + gx];
        } else {
            SRAW(r, c4i + 0) = im[gr * HW + refl(gx + 0)];
            SRAW(r, c4i + 1) = im[gr * HW + refl(gx + 1)];
            SRAW(r, c4i + 2) = im[gr * HW + refl(gx + 2)];
            SRAW(r, c4i + 3) = im[gr * HW + refl(gx + 3)];
        }
    }
    // Center: one STS.128 from registers per thread.
    *(float4*)&SRAW(row + 8, c4 + 8) = *(const float4*)raw;

    // Phase 1.5 (pre-barrier): 6 elementwise channels from own registers.
    {
        __stcs((float4*)&out[p], *(const float4*)raw);
        float t4[4], off4[4];
        #pragma unroll
        for (int j = 0; j < 4; j++) {
            float off = (raw[j] - bgv[j]) * rsqrtf(bgv[j]);
            t4[j] = __logf(fmaxf(off + 1.0f, 1.0f));
            off4[j] = off;
        }
        __stcs((float4*)&out[p + 1 * CH], *(const float4*)t4);
        #pragma unroll
        for (int j = 0; j < 4; j++) t4[j] = __logf(fmaxf(off4[j], 1.0f));
        __stcs((float4*)&out[p + 2 * CH], *(const float4*)t4);
        #pragma unroll
        for (int j = 0; j < 4; j++) t4[j] = fast_asinh((raw[j] - th0) * sc0);
        __stcs((float4*)&out[p + 4 * CH], *(const float4*)t4);
        #pragma unroll
        for (int j = 0; j < 4; j++) t4[j] = fast_asinh((raw[j] - th1) * sc1);
        __stcs((float4*)&out[p + 5 * CH], *(const float4*)t4);
        #pragma unroll
        for (int j = 0; j < 4; j++) t4[j] = fast_asinh((raw[j] - th2) * sc2);
        __stcs((float4*)&out[p + 6 * CH], *(const float4*)t4);
    }
    __syncthreads();

    // Phase 2: horizontal 9-sums of raw, 48 rows x 72 cols (4 outs/task)
    for (int t = tid; t < RSY * (MSX / 4); t += NT) {           // 864 tasks
        int r = t / 18, c4i = (t - r * 18) * 4;
        float4 a = *(const float4*)&SRAW(r, c4i);
        float4 b = *(const float4*)&SRAW(r, c4i + 4);
        float4 c = *(const float4*)&SRAW(r, c4i + 8);
        float s0 = ((a.x + a.y) + (a.z + a.w)) + ((b.x + b.y) + (b.z + b.w)) + c.x;
        float s1 = s0 - a.x + c.y;
        float s2 = s1 - a.y + c.z;
        float s3 = s2 - a.z + c.w;
        *(float4*)&SHS(r, c4i) = make_float4(s0, s1, s2, s3);
    }
    __syncthreads();

    // Phase 3: vertical 9-sums -> mean -> res, 40x72.
    // float2 column-pairs, 8-row sliding groups (180 tasks, <=1 per thread).
    // Retain taps t0-t2; re-load t3-t6 at their subtraction points.
    if (tid < 5 * (MSX / 2)) {
        int rg = tid / 36, cp = tid - rg * 36;
        int c = cp * 2, r0 = rg * 8;
        float2 t0 = LD2(SHS(r0, c)), t1 = LD2(SHS(r0 + 1, c)), t2 = LD2(SHS(r0 + 2, c));
        float2 s = make_float2(t0.x + t1.x + t2.x, t0.y + t1.y + t2.y);
        #pragma unroll
        for (int k = 3; k < 9; k++) {
            float2 w = LD2(SHS(r0 + k, c));
            s.x += w.x; s.y += w.y;
        }
        float2 rv = LD2(SRAW(r0 + 4, c + 4));
        ST2(SRES(r0 + 0, c)) = make_float2(rv.x - s.x * inv81, rv.y - s.y * inv81);
        float2 w;
        w = LD2(SHS(r0 + 9, c));  s.x += w.x - t0.x; s.y += w.y - t0.y;
        rv = LD2(SRAW(r0 + 5, c + 4));
        ST2(SRES(r0 + 1, c)) = make_float2(rv.x - s.x * inv81, rv.y - s.y * inv81);
        w = LD2(SHS(r0 + 10, c)); s.x += w.x - t1.x; s.y += w.y - t1.y;
        rv = LD2(SRAW(r0 + 6, c + 4));
        ST2(SRES(r0 + 2, c)) = make_float2(rv.x - s.x * inv81, rv.y - s.y * inv81);
        w = LD2(SHS(r0 + 11, c)); s.x += w.x - t2.x; s.y += w.y - t2.y;
        rv = LD2(SRAW(r0 + 7, c + 4));
        ST2(SRES(r0 + 3, c)) = make_float2(rv.x - s.x * inv81, rv.y - s.y * inv81);
        #pragma unroll
        for (int j = 4; j < 8; j++) {
            float2 wn = LD2(SHS(r0 + 8 + j, c));
            float2 wo = LD2(SHS(r0 + j - 1, c));
            s.x += wn.x - wo.x; s.y += wn.y - wo.y;
            rv = LD2(SRAW(r0 + 4 + j, c + 4));
            ST2(SRES(r0 + j, c)) = make_float2(rv.x - s.x * inv81, rv.y - s.y * inv81);
        }
    }
    __syncthreads();

    // Phase 4: VERTICAL-FIRST variance sums. scs[r][c] = sum_k res^2[r+k][c],
    // 32 rows x 72 cols, float2 column-pairs, 8-row sliding groups (144 tasks).
    if (tid < 4 * (MSX / 2)) {
        int rg = tid / 36, cp = tid - rg * 36;
        int c = cp * 2, r0 = rg * 8;
        float2 w0 = LD2(SRES(r0, c)), w1 = LD2(SRES(r0 + 1, c)), w2 = LD2(SRES(r0 + 2, c));
        float2 q0 = make_float2(w0.x * w0.x, w0.y * w0.y);
        float2 q1 = make_float2(w1.x * w1.x, w1.y * w1.y);
        float2 q2 = make_float2(w2.x * w2.x, w2.y * w2.y);
        float2 s = make_float2(q0.x + q1.x + q2.x, q0.y + q1.y + q2.y);
        #pragma unroll
        for (int k = 3; k < 9; k++) {
            float2 w = LD2(SRES(r0 + k, c));
            s.x = fmaf(w.x, w.x, s.x); s.y = fmaf(w.y, w.y, s.y);
        }
        ST2(SCS(r0 + 0, c)) = s;
        float2 w;
        w = LD2(SRES(r0 + 9, c));
        s.x = fmaf(w.x, w.x, s.x) - q0.x; s.y = fmaf(w.y, w.y, s.y) - q0.y;
        ST2(SCS(r0 + 1, c)) = s;
        w = LD2(SRES(r0 + 10, c));
        s.x = fmaf(w.x, w.x, s.x) - q1.x; s.y = fmaf(w.y, w.y, s.y) - q1.y;
        ST2(SCS(r0 + 2, c)) = s;
        w = LD2(SRES(r0 + 11, c));
        s.x = fmaf(w.x, w.x, s.x) - q2.x; s.y = fmaf(w.y, w.y, s.y) - q2.y;
        ST2(SCS(r0 + 3, c)) = s;
        #pragma unroll
        for (int j = 4; j < 8; j++) {
            float2 wn = LD2(SRES(r0 + 8 + j, c));
            float2 wo = LD2(SRES(r0 + j - 1, c));
            s.x = fmaf(wn.x, wn.x, s.x) - wo.x * wo.x;
            s.y = fmaf(wn.y, wn.y, s.y) - wo.y * wo.y;
            ST2(SCS(r0 + j, c)) = s;
        }
    }
    __syncthreads();

    // Phase 5: horizontal 9-sum of scs in registers + CLAHE store.
    {
        float q[12];
        *(float4*)&q[0] = *(const float4*)&SCS(row, c4);
        *(float4*)&q[4] = *(const float4*)&SCS(row, c4 + 4);
        *(float4*)&q[8] = *(const float4*)&SCS(row, c4 + 8);
        float s0 = ((q[0] + q[1]) + (q[2] + q[3])) +
                   ((q[4] + q[5]) + (q[6] + q[7])) + q[8];
        float s1 = s0 - q[0] + q[9];
        float s2 = s1 - q[1] + q[10];
        float s3 = s2 - q[2] + q[11];

        float res4[4], cl[4];
        *(float4*)res4 = *(const float4*)&SRES(row + 4, c4 + 4);
        cl[0] = res4[0] * rsqrtf(fmaxf(s0 * inv81, 1.0f));
        cl[1] = res4[1] * rsqrtf(fmaxf(s1 * inv81, 1.0f));
        cl[2] = res4[2] * rsqrtf(fmaxf(s2 * inv81, 1.0f));
        cl[3] = res4[3] * rsqrtf(fmaxf(s3 * inv81, 1.0f));
        __stcs((float4*)&out[p + 3 * CH], *(const float4*)cl);
    }
}

extern "C" void kernel_launch(void* const* d_in, const int* in_sizes, int n_in,
                              void* d_out, int out_size) {
    const float* img = (const float*)d_in[0];
    const float* bg  = (const float*)d_in[1];
    const float* thr = (const float*)d_in[2];
    const float* scl = (const float*)d_in[3];
    float* out = (float*)d_out;
    cudaFuncSetAttribute(imgnorm_kernel,
                         cudaFuncAttributeMaxDynamicSharedMemorySize, SMEM_BYTES);
    dim3 grid(HW / TX, HW / TY, 8 * 5);
    imgnorm_kernel<<<grid, NT, SMEM_BYTES>>>(img, bg, thr, scl, out);
}